// round 5
// baseline (speedup 1.0000x reference)
#include <cuda_runtime.h>

// ---------------------------------------------------------------------------
// Problem constants
//   x[8192,512], kg[200000,64], idx/mask[8192,50]
//   Wkg[64,64], W1a[512,128], W1b[128,512], W1c[512,128], W1d[128,64], W2[64,1024]
//   out[8192,1024] fp32
// ---------------------------------------------------------------------------

// Scratch (allocation-free: __device__ globals)
__device__ float g_h1[8192 * 128];
__device__ float g_h2[8192 * 512];
__device__ float g_h3[8192 * 128];
__device__ float g_know[8192 * 64];
__device__ float g_h[8192 * 64];

// ---------------------------------------------------------------------------
// Knowledge branch body: know[b,c] = sum_k mask[b,k]*relu(kg[idx[b,k],:]@Wkg[:,c]+bkg[c])
// One warp per b (8 warps/block). Lane computes cols (lane, lane+32).
// ---------------------------------------------------------------------------
__device__ __forceinline__
void knowledge_body(int bx, const float* __restrict__ kg, const int* __restrict__ idx,
                    const int* __restrict__ mask, const float* __restrict__ Wkg,
                    const float* __restrict__ bkg, float* __restrict__ out) {
    __shared__ float2 wk2[64][32];      // wk2[d][c] = (Wkg[d][c], Wkg[d][c+32])
    __shared__ float2 bk2[32];
    __shared__ float  rowbuf[8][68];

    const int tid = threadIdx.x;
    for (int i = tid; i < 64 * 32; i += 256) {
        int d = i >> 5, c = i & 31;
        wk2[d][c] = make_float2(Wkg[d * 64 + c], Wkg[d * 64 + c + 32]);
    }
    if (tid < 32) bk2[tid] = make_float2(bkg[tid], bkg[tid + 32]);
    __syncthreads();

    const int warp = tid >> 5, lane = tid & 31;
    const int b = bx * 8 + warp;
    float* rb = rowbuf[warp];

    // Lane l holds k=l and (l<18) k=l+32; broadcast via shfl in the loop.
    int my_i0 = __ldg(idx  + (size_t)b * 50 + lane);
    int my_m0 = __ldg(mask + (size_t)b * 50 + lane);
    int my_i1 = 0, my_m1 = 0;
    if (lane < 18) {
        my_i1 = __ldg(idx  + (size_t)b * 50 + 32 + lane);
        my_m1 = __ldg(mask + (size_t)b * 50 + 32 + lane);
    }

    float s0 = 0.f, s1 = 0.f;
    const float bb0 = bk2[lane].x, bb1 = bk2[lane].y;

    #pragma unroll 2
    for (int k = 0; k < 50; k++) {
        int src = k & 31;
        int m = __shfl_sync(0xffffffffu, (k < 32) ? my_m0 : my_m1, src);
        if (m) {                                         // warp-uniform branch
            int r = __shfl_sync(0xffffffffu, (k < 32) ? my_i0 : my_i1, src);
            float2 v = *(const float2*)(kg + (size_t)r * 64 + lane * 2);
            __syncwarp();
            *(float2*)&rb[lane * 2] = v;
            __syncwarp();
            float a0 = bb0, a1 = bb1;
            #pragma unroll
            for (int d4 = 0; d4 < 16; d4++) {
                float4 rv = *(const float4*)&rb[d4 * 4];
                float rr[4] = {rv.x, rv.y, rv.z, rv.w};
                #pragma unroll
                for (int q = 0; q < 4; q++) {
                    float2 w = wk2[d4 * 4 + q][lane];
                    a0 = fmaf(rr[q], w.x, a0);
                    a1 = fmaf(rr[q], w.y, a1);
                }
            }
            s0 += fmaxf(a0, 0.f);
            s1 += fmaxf(a1, 0.f);
        }
    }
    out[(size_t)b * 64 + lane]      = s0;
    out[(size_t)b * 64 + lane + 32] = s1;
}

// ---------------------------------------------------------------------------
// SGEMM body: C[32,64] tile = act(A@W + bias) (+X). 256 threads, 2x4 microtile.
//   As[k][m] transposed, stride 34 (conflict-free LDS.64 frag reads)
//   Bs[k][n] stride 64
// ---------------------------------------------------------------------------
template<bool RELU, bool ADDX>
__device__ __forceinline__
void sgemm_body(int m0, int n0, const float* __restrict__ A, const float* __restrict__ W,
                const float* __restrict__ bias, const float* __restrict__ X,
                float* __restrict__ C, int K, int N) {
    __shared__ float As[32][34];        // As[k][m]
    __shared__ float Bs[32][64];        // Bs[k][n]

    const int tid = threadIdx.x;
    const int tc = tid & 15;            // col group (tc*4)
    const int tr = tid >> 4;            // row pair (tr*2)
    const int a_row = tid >> 3;         // m: 0..31
    const int a_col = (tid & 7) << 2;   // k: 0..28
    const int b_row = tid >> 4;         // k: 0..15 (+16)
    const int b_col = (tid & 15) << 2;  // n: 0..60

    const float* Ap  = A + (size_t)(m0 + a_row) * K + a_col;
    const float* Wp0 = W + (size_t)b_row * N + n0 + b_col;
    const float* Wp1 = Wp0 + (size_t)16 * N;

    const float4 bb = *(const float4*)(bias + n0 + tc * 4);

    float acc[2][4] = {};

    for (int k0 = 0; k0 < K; k0 += 32) {
        float4 av  = *(const float4*)(Ap + k0);
        float4 bv0 = *(const float4*)(Wp0 + (size_t)k0 * N);
        float4 bv1 = *(const float4*)(Wp1 + (size_t)k0 * N);
        __syncthreads();
        As[a_col + 0][a_row] = av.x;    // transpose scatter, <=2-way conflict
        As[a_col + 1][a_row] = av.y;
        As[a_col + 2][a_row] = av.z;
        As[a_col + 3][a_row] = av.w;
        *(float4*)&Bs[b_row][b_col]      = bv0;
        *(float4*)&Bs[b_row + 16][b_col] = bv1;
        __syncthreads();

        #pragma unroll
        for (int dk = 0; dk < 32; dk++) {
            float2 a2 = *(const float2*)&As[dk][tr * 2];   // conflict-free LDS.64
            float4 b4 = *(const float4*)&Bs[dk][tc * 4];   // conflict-free LDS.128
            acc[0][0] = fmaf(a2.x, b4.x, acc[0][0]);
            acc[0][1] = fmaf(a2.x, b4.y, acc[0][1]);
            acc[0][2] = fmaf(a2.x, b4.z, acc[0][2]);
            acc[0][3] = fmaf(a2.x, b4.w, acc[0][3]);
            acc[1][0] = fmaf(a2.y, b4.x, acc[1][0]);
            acc[1][1] = fmaf(a2.y, b4.y, acc[1][1]);
            acc[1][2] = fmaf(a2.y, b4.z, acc[1][2]);
            acc[1][3] = fmaf(a2.y, b4.w, acc[1][3]);
        }
    }

    #pragma unroll
    for (int i = 0; i < 2; i++) {
        const int m = m0 + tr * 2 + i;
        float o0 = acc[i][0] + bb.x;
        float o1 = acc[i][1] + bb.y;
        float o2 = acc[i][2] + bb.z;
        float o3 = acc[i][3] + bb.w;
        if (RELU) {
            o0 = fmaxf(o0, 0.f); o1 = fmaxf(o1, 0.f);
            o2 = fmaxf(o2, 0.f); o3 = fmaxf(o3, 0.f);
        }
        if (ADDX) {
            float4 xv = *(const float4*)(X + (size_t)m * N + n0 + tc * 4);
            o0 += xv.x; o1 += xv.y; o2 += xv.z; o3 += xv.w;
        }
        float4 ov = make_float4(o0, o1, o2, o3);
        *(float4*)(C + (size_t)m * N + n0 + tc * 4) = ov;
    }
}

template<bool RELU, bool ADDX>
__global__ __launch_bounds__(256)
void sgemm_kernel(const float* __restrict__ A, const float* __restrict__ W,
                  const float* __restrict__ bias, const float* __restrict__ X,
                  float* __restrict__ C, int K, int N) {
    sgemm_body<RELU, ADDX>(blockIdx.x * 32, blockIdx.y * 64, A, W, bias, X, C, K, N);
}

// Fused launch: blocks [0,1024) run the knowledge branch, [1024,1536) run layer 1a.
// They are independent; fusing them fills the chip (knowledge blocks first = long pole).
__global__ __launch_bounds__(256)
void fused_know_1a_kernel(const float* __restrict__ kg, const int* __restrict__ idx,
                          const int* __restrict__ mask, const float* __restrict__ Wkg,
                          const float* __restrict__ bkg, float* __restrict__ know,
                          const float* __restrict__ x, const float* __restrict__ W1a,
                          const float* __restrict__ b1a, float* __restrict__ h1) {
    if (blockIdx.x < 1024) {
        knowledge_body(blockIdx.x, kg, idx, mask, Wkg, bkg, know);
    } else {
        int b = blockIdx.x - 1024;                      // 0..511
        sgemm_body<true, false>((b >> 1) * 32, (b & 1) * 64, x, W1a, b1a, nullptr, h1, 512, 128);
    }
}

// ---------------------------------------------------------------------------
// Launch
// ---------------------------------------------------------------------------
extern "C" void kernel_launch(void* const* d_in, const int* in_sizes, int n_in,
                              void* d_out, int out_size) {
    const float* x    = (const float*)d_in[0];
    const float* kg   = (const float*)d_in[1];
    const int*   idx  = (const int*)  d_in[2];
    const int*   mask = (const int*)  d_in[3];
    const float* Wkg  = (const float*)d_in[4];
    const float* bkg  = (const float*)d_in[5];
    const float* W1a  = (const float*)d_in[6];
    const float* b1a  = (const float*)d_in[7];
    const float* W1b  = (const float*)d_in[8];
    const float* b1b  = (const float*)d_in[9];
    const float* W1c  = (const float*)d_in[10];
    const float* b1c  = (const float*)d_in[11];
    const float* W1d  = (const float*)d_in[12];
    const float* b1d  = (const float*)d_in[13];
    const float* W2   = (const float*)d_in[14];
    const float* b2   = (const float*)d_in[15];
    float* out = (float*)d_out;

    float *h1, *h2, *h3, *know, *h;
    cudaGetSymbolAddress((void**)&h1,   g_h1);
    cudaGetSymbolAddress((void**)&h2,   g_h2);
    cudaGetSymbolAddress((void**)&h3,   g_h3);
    cudaGetSymbolAddress((void**)&know, g_know);
    cudaGetSymbolAddress((void**)&h,    g_h);

    // knowledge (1024 blocks) + layer 1a (512 blocks) fused
    fused_know_1a_kernel<<<1536, 256>>>(kg, idx, mask, Wkg, bkg, know, x, W1a, b1a, h1);

    // Dense MLP chain (M=8192 -> 256 row-blocks of 32)
    sgemm_kernel<true,  false><<<dim3(256, 8),  256>>>(h1, W1b, b1b, nullptr, h2, 128, 512);
    sgemm_kernel<true,  false><<<dim3(256, 2),  256>>>(h2, W1c, b1c, nullptr, h3, 512, 128);
    // h = relu(h3 @ W1d + b1d) + knowledge
    sgemm_kernel<true,  true ><<<dim3(256, 1),  256>>>(h3, W1d, b1d, know,    h,  128, 64);
    // out = h @ W2 + b2
    sgemm_kernel<false, false><<<dim3(256, 16), 256>>>(h,  W2,  b2,  nullptr, out, 64, 1024);
}

// round 11
// speedup vs baseline: 1.2289x; 1.2289x over previous
#include <cuda_runtime.h>

// ---------------------------------------------------------------------------
// Problem constants
//   x[8192,512], kg[200000,64], idx/mask[8192,50]
//   Wkg[64,64], W1a[512,128], W1b[128,512], W1c[512,128], W1d[128,64], W2[64,1024]
//   out[8192,1024] fp32
// ---------------------------------------------------------------------------

// Scratch (allocation-free: __device__ globals)
__device__ float g_h1[8192 * 128];
__device__ float g_h2[8192 * 512];
__device__ float g_h3[8192 * 128];
__device__ float g_know[8192 * 64];
__device__ float g_h[8192 * 64];

// ---------------------------------------------------------------------------
// Knowledge branch: know[b,c] = sum_k mask[b,k]*relu(kg[idx[b,k],:]@Wkg[:,c]+bkg[c])
// One warp per b. Lane computes cols (lane, lane+32). Mask bits gathered via
// ballot into a 50-bit word; iterate set bits only, with depth-1 LDG prefetch
// so the next row's gather overlaps the current row's 128 FMAs.
// ---------------------------------------------------------------------------
__device__ __forceinline__
void knowledge_body(int bx, const float* __restrict__ kg, const int* __restrict__ idx,
                    const int* __restrict__ mask, const float* __restrict__ Wkg,
                    const float* __restrict__ bkg, float* __restrict__ out) {
    __shared__ float2 wk2[64][32];      // wk2[d][c] = (Wkg[d][c], Wkg[d][c+32])
    __shared__ float2 bk2[32];
    __shared__ float  rowbuf[8][68];

    const int tid = threadIdx.x;
    for (int i = tid; i < 64 * 32; i += 256) {
        int d = i >> 5, c = i & 31;
        wk2[d][c] = make_float2(Wkg[d * 64 + c], Wkg[d * 64 + c + 32]);
    }
    if (tid < 32) bk2[tid] = make_float2(bkg[tid], bkg[tid + 32]);
    __syncthreads();

    const int warp = tid >> 5, lane = tid & 31;
    const int b = bx * 8 + warp;
    float* rb = rowbuf[warp];

    // Lane l holds k=l and (l<18) k=l+32.
    int my_i0 = __ldg(idx  + (size_t)b * 50 + lane);
    int my_m0 = __ldg(mask + (size_t)b * 50 + lane);
    int my_i1 = 0, my_m1 = 0;
    if (lane < 18) {
        my_i1 = __ldg(idx  + (size_t)b * 50 + 32 + lane);
        my_m1 = __ldg(mask + (size_t)b * 50 + 32 + lane);
    }

    unsigned mlo = __ballot_sync(0xffffffffu, my_m0 != 0);
    unsigned mhi = __ballot_sync(0xffffffffu, my_m1 != 0);   // lanes>=18 contribute 0
    unsigned long long mm = (unsigned long long)mlo | ((unsigned long long)mhi << 32);

    float s0 = 0.f, s1 = 0.f;
    const float bb0 = bk2[lane].x, bb1 = bk2[lane].y;

    if (mm) {
        int k = __ffsll(mm) - 1; mm &= mm - 1;
        int r = __shfl_sync(0xffffffffu, (k < 32) ? my_i0 : my_i1, k & 31);
        float2 v = *(const float2*)(kg + (size_t)r * 64 + lane * 2);
        for (;;) {
            *(float2*)&rb[lane * 2] = v;
            const bool more = (mm != 0);
            float2 vn = make_float2(0.f, 0.f);
            if (more) {                                  // prefetch next row (uniform)
                int k2 = __ffsll(mm) - 1; mm &= mm - 1;
                int r2 = __shfl_sync(0xffffffffu, (k2 < 32) ? my_i0 : my_i1, k2 & 31);
                vn = *(const float2*)(kg + (size_t)r2 * 64 + lane * 2);
            }
            __syncwarp();
            float a0 = bb0, a1 = bb1;
            #pragma unroll
            for (int d4 = 0; d4 < 16; d4++) {
                float4 rv = *(const float4*)&rb[d4 * 4];
                float rr[4] = {rv.x, rv.y, rv.z, rv.w};
                #pragma unroll
                for (int q = 0; q < 4; q++) {
                    float2 w = wk2[d4 * 4 + q][lane];
                    a0 = fmaf(rr[q], w.x, a0);
                    a1 = fmaf(rr[q], w.y, a1);
                }
            }
            s0 += fmaxf(a0, 0.f);
            s1 += fmaxf(a1, 0.f);
            if (!more) break;
            __syncwarp();                                // rb reuse guard
            v = vn;
        }
    }
    out[(size_t)b * 64 + lane]      = s0;
    out[(size_t)b * 64 + lane + 32] = s1;
}

// ---------------------------------------------------------------------------
// SGEMM: C[64,64] tile = act(A@W + bias) (+X). 256 threads, 4x4 microtile,
// DOUBLE-BUFFERED smem: one barrier per k-iter, LDG for iter i+1 issued
// before the math of iter i.
//   As[m][36] (frag reads are warp broadcasts; stores phase-conflict-free)
//   Bs[k][64]
// ---------------------------------------------------------------------------
template<bool RELU, bool ADDX>
__device__ __forceinline__
void sgemm_body(int m0, int n0, const float* __restrict__ A, const float* __restrict__ W,
                const float* __restrict__ bias, const float* __restrict__ X,
                float* __restrict__ C, int K, int N) {
    __shared__ float As[2][64][36];
    __shared__ float Bs[2][32][64];

    const int tid = threadIdx.x;
    const int tc = tid & 15;            // col group (tc*4)
    const int tr = tid >> 4;            // row group (tr*4)
    const int a_row = tid >> 3;         // 0..31 (and +32)
    const int a_col = (tid & 7) << 2;   // 0..28
    const int b_row = tid >> 4;         // 0..15 (and +16)
    const int b_col = (tid & 15) << 2;  // 0..60

    const float* Ap0 = A + (size_t)(m0 + a_row) * K + a_col;
    const float* Ap1 = Ap0 + (size_t)32 * K;
    const float* Wp0 = W + (size_t)b_row * N + n0 + b_col;
    const float* Wp1 = Wp0 + (size_t)16 * N;

    const int nIter = K >> 5;
    float acc[4][4] = {};

    // Prologue: load + store tile 0 into buffer 0.
    {
        float4 av0 = *(const float4*)(Ap0);
        float4 av1 = *(const float4*)(Ap1);
        float4 bv0 = *(const float4*)(Wp0);
        float4 bv1 = *(const float4*)(Wp1);
        *(float4*)&As[0][a_row][a_col]      = av0;
        *(float4*)&As[0][a_row + 32][a_col] = av1;
        *(float4*)&Bs[0][b_row][b_col]      = bv0;
        *(float4*)&Bs[0][b_row + 16][b_col] = bv1;
    }

    for (int i = 0; i < nIter; i++) {
        __syncthreads();
        const int cur = i & 1, nxt = cur ^ 1;

        float4 av0, av1, bv0, bv1;
        const bool more = (i + 1 < nIter);
        if (more) {                                      // prefetch next tile (LDG early)
            const int k0 = (i + 1) << 5;
            av0 = *(const float4*)(Ap0 + k0);
            av1 = *(const float4*)(Ap1 + k0);
            bv0 = *(const float4*)(Wp0 + (size_t)k0 * N);
            bv1 = *(const float4*)(Wp1 + (size_t)k0 * N);
        }

        #pragma unroll
        for (int kk = 0; kk < 32; kk += 4) {
            float a[4][4], bfr[4][4];
            #pragma unroll
            for (int ii = 0; ii < 4; ii++) {
                float4 t = *(const float4*)&As[cur][tr * 4 + ii][kk];
                a[ii][0] = t.x; a[ii][1] = t.y; a[ii][2] = t.z; a[ii][3] = t.w;
            }
            #pragma unroll
            for (int dk = 0; dk < 4; dk++) {
                float4 t = *(const float4*)&Bs[cur][kk + dk][tc * 4];
                bfr[dk][0] = t.x; bfr[dk][1] = t.y; bfr[dk][2] = t.z; bfr[dk][3] = t.w;
            }
            #pragma unroll
            for (int ii = 0; ii < 4; ii++)
                #pragma unroll
                for (int dk = 0; dk < 4; dk++)
                    #pragma unroll
                    for (int j = 0; j < 4; j++)
                        acc[ii][j] = fmaf(a[ii][dk], bfr[dk][j], acc[ii][j]);
        }

        if (more) {                                      // stage into alternate buffer
            *(float4*)&As[nxt][a_row][a_col]      = av0;
            *(float4*)&As[nxt][a_row + 32][a_col] = av1;
            *(float4*)&Bs[nxt][b_row][b_col]      = bv0;
            *(float4*)&Bs[nxt][b_row + 16][b_col] = bv1;
        }
    }

    // Epilogue: bias (+relu) (+X)
    #pragma unroll
    for (int i = 0; i < 4; i++) {
        const int m = m0 + tr * 4 + i;
        float o[4];
        #pragma unroll
        for (int j = 0; j < 4; j++) {
            const int n = n0 + tc * 4 + j;
            float v = acc[i][j] + bias[n];
            if (RELU) v = fmaxf(v, 0.f);
            if (ADDX) v += X[(size_t)m * N + n];
            o[j] = v;
        }
        *(float4*)(C + (size_t)m * N + n0 + tc * 4) = *(float4*)o;
    }
}

template<bool RELU, bool ADDX>
__global__ __launch_bounds__(256)
void sgemm_kernel(const float* __restrict__ A, const float* __restrict__ W,
                  const float* __restrict__ bias, const float* __restrict__ X,
                  float* __restrict__ C, int K, int N) {
    sgemm_body<RELU, ADDX>(blockIdx.x * 64, blockIdx.y * 64, A, W, bias, X, C, K, N);
}

// Fused: blocks [0,1024) = knowledge branch, [1024,1280) = layer 1a (128x2 tiles).
__global__ __launch_bounds__(256)
void fused_know_1a_kernel(const float* __restrict__ kg, const int* __restrict__ idx,
                          const int* __restrict__ mask, const float* __restrict__ Wkg,
                          const float* __restrict__ bkg, float* __restrict__ know,
                          const float* __restrict__ x, const float* __restrict__ W1a,
                          const float* __restrict__ b1a, float* __restrict__ h1) {
    if (blockIdx.x < 1024) {
        knowledge_body(blockIdx.x, kg, idx, mask, Wkg, bkg, know);
    } else {
        int b = blockIdx.x - 1024;                      // 0..255
        sgemm_body<true, false>((b >> 1) * 64, (b & 1) * 64, x, W1a, b1a, nullptr, h1, 512, 128);
    }
}

// ---------------------------------------------------------------------------
// Launch
// ---------------------------------------------------------------------------
extern "C" void kernel_launch(void* const* d_in, const int* in_sizes, int n_in,
                              void* d_out, int out_size) {
    const float* x    = (const float*)d_in[0];
    const float* kg   = (const float*)d_in[1];
    const int*   idx  = (const int*)  d_in[2];
    const int*   mask = (const int*)  d_in[3];
    const float* Wkg  = (const float*)d_in[4];
    const float* bkg  = (const float*)d_in[5];
    const float* W1a  = (const float*)d_in[6];
    const float* b1a  = (const float*)d_in[7];
    const float* W1b  = (const float*)d_in[8];
    const float* b1b  = (const float*)d_in[9];
    const float* W1c  = (const float*)d_in[10];
    const float* b1c  = (const float*)d_in[11];
    const float* W1d  = (const float*)d_in[12];
    const float* b1d  = (const float*)d_in[13];
    const float* W2   = (const float*)d_in[14];
    const float* b2   = (const float*)d_in[15];
    float* out = (float*)d_out;

    float *h1, *h2, *h3, *know, *h;
    cudaGetSymbolAddress((void**)&h1,   g_h1);
    cudaGetSymbolAddress((void**)&h2,   g_h2);
    cudaGetSymbolAddress((void**)&h3,   g_h3);
    cudaGetSymbolAddress((void**)&know, g_know);
    cudaGetSymbolAddress((void**)&h,    g_h);

    // knowledge (1024 blocks) + layer 1a (256 tile-blocks) fused
    fused_know_1a_kernel<<<1280, 256>>>(kg, idx, mask, Wkg, bkg, know, x, W1a, b1a, h1);

    // Dense MLP chain (M=8192 -> 128 row-blocks of 64)
    sgemm_kernel<true,  false><<<dim3(128, 8),  256>>>(h1, W1b, b1b, nullptr, h2, 128, 512);
    sgemm_kernel<true,  false><<<dim3(128, 2),  256>>>(h2, W1c, b1c, nullptr, h3, 512, 128);
    // h = relu(h3 @ W1d + b1d) + knowledge
    sgemm_kernel<true,  true ><<<dim3(128, 1),  256>>>(h3, W1d, b1d, know,    h,  128, 64);
    // out = h @ W2 + b2
    sgemm_kernel<false, false><<<dim3(128, 16), 256>>>(h,  W2,  b2,  nullptr, out, 64, 1024);
}

// round 16
// speedup vs baseline: 1.2313x; 1.0019x over previous
#include <cuda_runtime.h>
#include <cuda_bf16.h>
#include <mma.h>
#include <cstdint>

using namespace nvcuda;

// ---------------------------------------------------------------------------
// KnowledgeMLP: x[8192,512], kg[200000,64], idx/mask[8192,50]
// GEMM chain on WMMA bf16x3 (HMMA, fp32 accum) — tcgen05 is unavailable under
// this harness's compute_103 PTX target (R15 ptxas evidence).
// Knowledge branch + tiny layer-1d on proven SIMT kernels.
// ---------------------------------------------------------------------------

__device__ float g_h1[8192 * 128];
__device__ float g_h2[8192 * 512];
__device__ float g_h3[8192 * 128];
__device__ float g_know[8192 * 64];
__device__ float g_h[8192 * 64];

// ---------------------------------------------------------------------------
// WMMA bf16x3 GEMM: C[64,64] tile = act(A[M,K]@W[K,N] + bias)
// A,W split hi/lo bf16; acc += Ah*Bh + Ah*Bl + Al*Bh (fp32 frags).
// 256 threads = 8 warps in 4(m) x 2(n); each warp: 16x32 of C (2 frags).
// ---------------------------------------------------------------------------
template<bool RELU>
__global__ __launch_bounds__(256)
void wmma_gemm_kernel(const float* __restrict__ A, const float* __restrict__ W,
                      const float* __restrict__ bias, float* __restrict__ C,
                      int K, int N) {
    __shared__ __nv_bfloat16 Ah[64][40], Al[64][40];   // [m][k], BK=32, pad->40
    __shared__ __nv_bfloat16 Bh[32][72], Bl[32][72];   // [k][n], BN=64, pad->72
    __shared__ float Cs[64][72];                       // epilogue staging

    const int tid  = threadIdx.x;
    const int warp = tid >> 5;
    const int wm   = warp >> 1;          // 0..3  (m strip: wm*16)
    const int wn   = warp & 1;           // 0..1  (n strip: wn*32)
    const int m0   = blockIdx.x * 64, n0 = blockIdx.y * 64;

    wmma::fragment<wmma::accumulator, 16, 16, 16, float> acc0, acc1;
    wmma::fill_fragment(acc0, 0.f);
    wmma::fill_fragment(acc1, 0.f);

    const int nChunks = K >> 5;
    for (int c = 0; c < nChunks; c++) {
        __syncthreads();                              // smem reuse guard

        // ---- A chunk 64x32: 2048 elems, 2 float4 per thread ----
        #pragma unroll
        for (int it = 0; it < 2; it++) {
            int idx = it * 1024 + tid * 4;
            int r = idx >> 5, cc = idx & 31;
            float4 v = *(const float4*)(A + (size_t)(m0 + r) * K + c * 32 + cc);
            float f[4] = {v.x, v.y, v.z, v.w};
            #pragma unroll
            for (int q = 0; q < 4; q++) {
                __nv_bfloat16 h = __float2bfloat16(f[q]);
                Ah[r][cc + q] = h;
                Al[r][cc + q] = __float2bfloat16(f[q] - __bfloat162float(h));
            }
        }
        // ---- B chunk 32x64: 2048 elems, 2 float4 per thread ----
        #pragma unroll
        for (int it = 0; it < 2; it++) {
            int idx = it * 1024 + tid * 4;
            int r = idx >> 6, cc = idx & 63;
            float4 v = *(const float4*)(W + (size_t)(c * 32 + r) * N + n0 + cc);
            float f[4] = {v.x, v.y, v.z, v.w};
            #pragma unroll
            for (int q = 0; q < 4; q++) {
                __nv_bfloat16 h = __float2bfloat16(f[q]);
                Bh[r][cc + q] = h;
                Bl[r][cc + q] = __float2bfloat16(f[q] - __bfloat162float(h));
            }
        }
        __syncthreads();

        // ---- 2 k-steps x 6 wmma (hh, hl, lh for each of 2 n-frags) ----
        #pragma unroll
        for (int ks = 0; ks < 2; ks++) {
            wmma::fragment<wmma::matrix_a, 16, 16, 16, __nv_bfloat16, wmma::row_major> a_h, a_l;
            wmma::load_matrix_sync(a_h, &Ah[wm * 16][ks * 16], 40);
            wmma::load_matrix_sync(a_l, &Al[wm * 16][ks * 16], 40);
            wmma::fragment<wmma::matrix_b, 16, 16, 16, __nv_bfloat16, wmma::row_major> b_h0, b_h1, b_l0, b_l1;
            wmma::load_matrix_sync(b_h0, &Bh[ks * 16][wn * 32],      72);
            wmma::load_matrix_sync(b_h1, &Bh[ks * 16][wn * 32 + 16], 72);
            wmma::load_matrix_sync(b_l0, &Bl[ks * 16][wn * 32],      72);
            wmma::load_matrix_sync(b_l1, &Bl[ks * 16][wn * 32 + 16], 72);
            wmma::mma_sync(acc0, a_h, b_h0, acc0);
            wmma::mma_sync(acc0, a_h, b_l0, acc0);
            wmma::mma_sync(acc0, a_l, b_h0, acc0);
            wmma::mma_sync(acc1, a_h, b_h1, acc1);
            wmma::mma_sync(acc1, a_h, b_l1, acc1);
            wmma::mma_sync(acc1, a_l, b_h1, acc1);
        }
    }

    // ---- Epilogue: frags -> smem -> bias(+relu) -> coalesced float4 stores ----
    wmma::store_matrix_sync(&Cs[wm * 16][wn * 32],      acc0, 72, wmma::mem_row_major);
    wmma::store_matrix_sync(&Cs[wm * 16][wn * 32 + 16], acc1, 72, wmma::mem_row_major);
    __syncthreads();
    #pragma unroll
    for (int it = 0; it < 4; it++) {
        int idx = it * 1024 + tid * 4;
        int r = idx >> 6, cc = idx & 63;
        float4 bv = *(const float4*)(bias + n0 + cc);
        float4 o;
        o.x = Cs[r][cc + 0] + bv.x;
        o.y = Cs[r][cc + 1] + bv.y;
        o.z = Cs[r][cc + 2] + bv.z;
        o.w = Cs[r][cc + 3] + bv.w;
        if (RELU) {
            o.x = fmaxf(o.x, 0.f); o.y = fmaxf(o.y, 0.f);
            o.z = fmaxf(o.z, 0.f); o.w = fmaxf(o.w, 0.f);
        }
        *(float4*)(C + (size_t)(m0 + r) * N + n0 + cc) = o;
    }
}

// ---------------------------------------------------------------------------
// Knowledge branch (SIMT, proven): ballot mask + depth-1 prefetch.
// ---------------------------------------------------------------------------
__global__ __launch_bounds__(256)
void knowledge_kernel(const float* __restrict__ kg, const int* __restrict__ idx,
                      const int* __restrict__ mask, const float* __restrict__ Wkg,
                      const float* __restrict__ bkg, float* __restrict__ out) {
    __shared__ float2 wk2[64][32];
    __shared__ float2 bk2[32];
    __shared__ float  rowbuf[8][68];

    const int tid = threadIdx.x;
    for (int i = tid; i < 64 * 32; i += 256) {
        int d = i >> 5, c = i & 31;
        wk2[d][c] = make_float2(Wkg[d * 64 + c], Wkg[d * 64 + c + 32]);
    }
    if (tid < 32) bk2[tid] = make_float2(bkg[tid], bkg[tid + 32]);
    __syncthreads();

    const int warp = tid >> 5, lane = tid & 31;
    const int b = blockIdx.x * 8 + warp;
    float* rb = rowbuf[warp];

    int my_i0 = __ldg(idx  + (size_t)b * 50 + lane);
    int my_m0 = __ldg(mask + (size_t)b * 50 + lane);
    int my_i1 = 0, my_m1 = 0;
    if (lane < 18) {
        my_i1 = __ldg(idx  + (size_t)b * 50 + 32 + lane);
        my_m1 = __ldg(mask + (size_t)b * 50 + 32 + lane);
    }
    unsigned mlo = __ballot_sync(0xffffffffu, my_m0 != 0);
    unsigned mhi = __ballot_sync(0xffffffffu, my_m1 != 0);
    unsigned long long mm = (unsigned long long)mlo | ((unsigned long long)mhi << 32);

    float s0 = 0.f, s1 = 0.f;
    const float bb0 = bk2[lane].x, bb1 = bk2[lane].y;

    if (mm) {
        int k = __ffsll(mm) - 1; mm &= mm - 1;
        int r = __shfl_sync(0xffffffffu, (k < 32) ? my_i0 : my_i1, k & 31);
        float2 v = *(const float2*)(kg + (size_t)r * 64 + lane * 2);
        for (;;) {
            *(float2*)&rb[lane * 2] = v;
            const bool more = (mm != 0);
            float2 vn = make_float2(0.f, 0.f);
            if (more) {
                int k2 = __ffsll(mm) - 1; mm &= mm - 1;
                int r2 = __shfl_sync(0xffffffffu, (k2 < 32) ? my_i0 : my_i1, k2 & 31);
                vn = *(const float2*)(kg + (size_t)r2 * 64 + lane * 2);
            }
            __syncwarp();
            float a0 = bb0, a1 = bb1;
            #pragma unroll
            for (int d4 = 0; d4 < 16; d4++) {
                float4 rv = *(const float4*)&rb[d4 * 4];
                float rr[4] = {rv.x, rv.y, rv.z, rv.w};
                #pragma unroll
                for (int q = 0; q < 4; q++) {
                    float2 w = wk2[d4 * 4 + q][lane];
                    a0 = fmaf(rr[q], w.x, a0);
                    a1 = fmaf(rr[q], w.y, a1);
                }
            }
            s0 += fmaxf(a0, 0.f);
            s1 += fmaxf(a1, 0.f);
            if (!more) break;
            __syncwarp();
            v = vn;
        }
    }
    out[(size_t)b * 64 + lane]      = s0;
    out[(size_t)b * 64 + lane + 32] = s1;
}

// ---------------------------------------------------------------------------
// SIMT SGEMM (double-buffered, proven) — only for the tiny 1d layer (N=64):
// h = relu(h3 @ W1d + b1d) + knowledge
// ---------------------------------------------------------------------------
__global__ __launch_bounds__(256)
void sgemm_1d_kernel(const float* __restrict__ A, const float* __restrict__ W,
                     const float* __restrict__ bias, const float* __restrict__ X,
                     float* __restrict__ C, int K, int N) {
    __shared__ float As[2][64][36];
    __shared__ float Bs[2][32][64];

    const int tid = threadIdx.x;
    const int tc = tid & 15, tr = tid >> 4;
    const int a_row = tid >> 3, a_col = (tid & 7) << 2;
    const int b_row = tid >> 4, b_col = (tid & 15) << 2;
    const int m0 = blockIdx.x * 64, n0 = 0;

    const float* Ap0 = A + (size_t)(m0 + a_row) * K + a_col;
    const float* Ap1 = Ap0 + (size_t)32 * K;
    const float* Wp0 = W + (size_t)b_row * N + n0 + b_col;
    const float* Wp1 = Wp0 + (size_t)16 * N;

    const int nIter = K >> 5;
    float acc[4][4] = {};
    {
        float4 av0 = *(const float4*)(Ap0);
        float4 av1 = *(const float4*)(Ap1);
        float4 bv0 = *(const float4*)(Wp0);
        float4 bv1 = *(const float4*)(Wp1);
        *(float4*)&As[0][a_row][a_col]      = av0;
        *(float4*)&As[0][a_row + 32][a_col] = av1;
        *(float4*)&Bs[0][b_row][b_col]      = bv0;
        *(float4*)&Bs[0][b_row + 16][b_col] = bv1;
    }
    for (int i = 0; i < nIter; i++) {
        __syncthreads();
        const int cur = i & 1, nxt = cur ^ 1;
        float4 av0, av1, bv0, bv1;
        const bool more = (i + 1 < nIter);
        if (more) {
            const int k0 = (i + 1) << 5;
            av0 = *(const float4*)(Ap0 + k0);
            av1 = *(const float4*)(Ap1 + k0);
            bv0 = *(const float4*)(Wp0 + (size_t)k0 * N);
            bv1 = *(const float4*)(Wp1 + (size_t)k0 * N);
        }
        #pragma unroll
        for (int kk = 0; kk < 32; kk += 4) {
            float a[4][4], bfr[4][4];
            #pragma unroll
            for (int ii = 0; ii < 4; ii++) {
                float4 t = *(const float4*)&As[cur][tr * 4 + ii][kk];
                a[ii][0] = t.x; a[ii][1] = t.y; a[ii][2] = t.z; a[ii][3] = t.w;
            }
            #pragma unroll
            for (int dk = 0; dk < 4; dk++) {
                float4 t = *(const float4*)&Bs[cur][kk + dk][tc * 4];
                bfr[dk][0] = t.x; bfr[dk][1] = t.y; bfr[dk][2] = t.z; bfr[dk][3] = t.w;
            }
            #pragma unroll
            for (int ii = 0; ii < 4; ii++)
                #pragma unroll
                for (int dk = 0; dk < 4; dk++)
                    #pragma unroll
                    for (int j = 0; j < 4; j++)
                        acc[ii][j] = fmaf(a[ii][dk], bfr[dk][j], acc[ii][j]);
        }
        if (more) {
            *(float4*)&As[nxt][a_row][a_col]      = av0;
            *(float4*)&As[nxt][a_row + 32][a_col] = av1;
            *(float4*)&Bs[nxt][b_row][b_col]      = bv0;
            *(float4*)&Bs[nxt][b_row + 16][b_col] = bv1;
        }
    }
    #pragma unroll
    for (int i = 0; i < 4; i++) {
        const int m = m0 + tr * 4 + i;
        float o[4];
        #pragma unroll
        for (int j = 0; j < 4; j++) {
            const int n = n0 + tc * 4 + j;
            float v = fmaxf(acc[i][j] + bias[n], 0.f);     // relu
            v += X[(size_t)m * N + n];                      // + knowledge
            o[j] = v;
        }
        *(float4*)(C + (size_t)m * N + n0 + tc * 4) = *(float4*)o;
    }
}

// ---------------------------------------------------------------------------
// Launch
// ---------------------------------------------------------------------------
extern "C" void kernel_launch(void* const* d_in, const int* in_sizes, int n_in,
                              void* d_out, int out_size) {
    const float* x    = (const float*)d_in[0];
    const float* kg   = (const float*)d_in[1];
    const int*   idx  = (const int*)  d_in[2];
    const int*   mask = (const int*)  d_in[3];
    const float* Wkg  = (const float*)d_in[4];
    const float* bkg  = (const float*)d_in[5];
    const float* W1a  = (const float*)d_in[6];
    const float* b1a  = (const float*)d_in[7];
    const float* W1b  = (const float*)d_in[8];
    const float* b1b  = (const float*)d_in[9];
    const float* W1c  = (const float*)d_in[10];
    const float* b1c  = (const float*)d_in[11];
    const float* W1d  = (const float*)d_in[12];
    const float* b1d  = (const float*)d_in[13];
    const float* W2   = (const float*)d_in[14];
    const float* b2   = (const float*)d_in[15];
    float* out = (float*)d_out;

    float *h1, *h2, *h3, *know, *h;
    cudaGetSymbolAddress((void**)&h1,   g_h1);
    cudaGetSymbolAddress((void**)&h2,   g_h2);
    cudaGetSymbolAddress((void**)&h3,   g_h3);
    cudaGetSymbolAddress((void**)&know, g_know);
    cudaGetSymbolAddress((void**)&h,    g_h);

    // Knowledge branch (SIMT)
    knowledge_kernel<<<1024, 256>>>(kg, idx, mask, Wkg, bkg, know);

    // Dense chain on WMMA bf16x3 (M=8192 -> 128 row-tiles of 64)
    wmma_gemm_kernel<true ><<<dim3(128, 2),  256>>>(x,  W1a, b1a, h1, 512, 128);
    wmma_gemm_kernel<true ><<<dim3(128, 8),  256>>>(h1, W1b, b1b, h2, 128, 512);
    wmma_gemm_kernel<true ><<<dim3(128, 2),  256>>>(h2, W1c, b1c, h3, 512, 128);
    // h = relu(h3 @ W1d + b1d) + knowledge  (SIMT; N=64)
    sgemm_1d_kernel<<<128, 256>>>(h3, W1d, b1d, know, h, 128, 64);
    // out = h @ W2 + b2 (no relu)
    wmma_gemm_kernel<false><<<dim3(128, 16), 256>>>(h, W2, b2, out, 64, 1024);
}